// round 5
// baseline (speedup 1.0000x reference)
#include <cuda_runtime.h>
#include <cstdint>

// BatchHardLoss round 4: FP8 e4m3 mma.sync (m16n8k32) GEMM + maskless f32x2
// poly-exp epilogue + exact fp32 same-class correction kernel.
// (tcgen05 is unavailable: harness ptxas targets sm_103 without the 'a' feature set.)

#define BATCH 8192
#define DIMK  256
#define NCLS  512
#define GAMMA 0.001f

static __device__ float g_all[BATCH];    // sum_j exp(+gamma*W_ij) over ALL j (incl self)
static __device__ float g_pos[BATCH];    // sum_{same,j!=i} exp(-gamma*W_ij)  (fp32 exact)
static __device__ float g_same[BATCH];   // sum_{same incl self} exp(+gamma*W_ij)
static __device__ int   g_cnt[NCLS];
static __device__ int   g_members[NCLS * 16];
static __device__ unsigned char g_Xf8[BATCH * DIMK];   // e4m3

constexpr int BM = 128;
constexpr int BN = 128;
constexpr int NSPLIT = 4;
constexpr int SPLIT_COLS = BATCH / NSPLIT;   // 2048
constexpr int NT = SPLIT_COLS / BN;          // 16 tiles per CTA
constexpr int KCHUNK = 16384;                // 128 rows x 128B swizzle chunk
constexpr int TILEB  = 32768;                // 128 rows x 256B (full K in fp8)
constexpr int SMEM_DYN = TILEB * 3 + 1024;   // A + 2xB + align pad

#define SW128(o) ((o) ^ (((o) >> 3) & 0x70))

__device__ __forceinline__ void cp_async16(uint32_t dst, const void* src) {
    asm volatile("cp.async.cg.shared.global [%0], [%1], 16;\n" :: "r"(dst), "l"(src));
}
#define CP_COMMIT() asm volatile("cp.async.commit_group;\n" ::: "memory")
#define CP_WAIT(N)  asm volatile("cp.async.wait_group %0;\n" :: "n"(N) : "memory")

// packed f32x2 ops
#define PACK2(d, a, b)    asm("mov.b64 %0, {%1,%2};" : "=l"(d) : "f"(a), "f"(b))
#define UNPACK2(a, b, s)  asm("mov.b64 {%0,%1}, %2;" : "=f"(a), "=f"(b) : "l"(s))
#define MUL2(d, a, b)     asm("mul.rn.f32x2 %0, %1, %2;" : "=l"(d) : "l"(a), "l"(b))
#define ADD2(d, a, b)     asm("add.rn.f32x2 %0, %1, %2;" : "=l"(d) : "l"(a), "l"(b))
#define FMA2(d, a, b, c)  asm("fma.rn.f32x2 %0, %1, %2, %3;" : "=l"(d) : "l"(a), "l"(b), "l"(c))

// ---------------- small kernels ----------------

__global__ void bhl_convert_kernel(const float* __restrict__ X, float* __restrict__ out) {
    int i = blockIdx.x * blockDim.x + threadIdx.x;   // float4 index, 0..524287
    float4 v = ((const float4*)X)[i];
    unsigned short lo, hi;
    asm("cvt.rn.satfinite.e4m3x2.f32 %0, %1, %2;" : "=h"(lo) : "f"(v.y), "f"(v.x));
    asm("cvt.rn.satfinite.e4m3x2.f32 %0, %1, %2;" : "=h"(hi) : "f"(v.w), "f"(v.z));
    ((uint32_t*)g_Xf8)[i] = (uint32_t)lo | ((uint32_t)hi << 16);
    if (i < BATCH) g_all[i] = 0.0f;
    if (i < NCLS)  g_cnt[i] = 0;
    if (i == 0)    out[0] = 0.0f;
}

__global__ void bhl_bucket_kernel(const int* __restrict__ T) {
    int i = blockIdx.x * blockDim.x + threadIdx.x;
    if (i < BATCH) {
        int c = T[i];
        int s = atomicAdd(&g_cnt[c], 1);
        if (s < 16) g_members[c * 16 + s] = i;
    }
}

// ---------------- main kernel ----------------

// load 128 rows x 256 bytes (fp8, full K) into [2 x 16KB SW128 chunks]
__device__ __forceinline__ void load_tile(uint32_t sdst, const char* srcRow0, int tid) {
#pragma unroll
    for (int i = 0; i < 8; i++) {
        int s = i * 256 + tid;            // 16B segment 0..2047
        int row = s >> 4;
        int seg = s & 15;                 // 0..15
        int chunk = seg >> 3, w = seg & 7;
        uint32_t soff = chunk * KCHUNK + SW128(row * 128 + w * 16);
        cp_async16(sdst + soff, srcRow0 + (size_t)row * 256 + seg * 16);
    }
}

__global__ __launch_bounds__(256, 2)
void bhl_main_kernel() {
    extern __shared__ char dynsmem[];
    __shared__ float sAll[BM];

    const int tid  = threadIdx.x;
    const int lane = tid & 31;
    const int wid  = tid >> 5;
    const int wm   = wid >> 2;           // 0..1
    const int wn   = wid & 3;            // 0..3
    const int rowBase  = blockIdx.x * BM;
    const int colBase0 = blockIdx.y * SPLIT_COLS;

    uint32_t sb = (uint32_t)__cvta_generic_to_shared(dynsmem);
    sb = (sb + 1023) & ~1023u;
    const uint32_t aBase = sb;
    const uint32_t bBase = sb + TILEB;

    if (tid < BM) sAll[tid] = 0.0f;

    const char* Xb = (const char*)g_Xf8;
    load_tile(aBase, Xb + (size_t)rowBase * 256, tid);
    load_tile(bBase, Xb + (size_t)colBase0 * 256, tid);
    CP_COMMIT();
    load_tile(bBase + TILEB, Xb + (size_t)(colBase0 + BN) * 256, tid);
    CP_COMMIT();

    float acc[4][4][4];
#pragma unroll
    for (int a = 0; a < 4; a++)
#pragma unroll
        for (int b = 0; b < 4; b++)
#pragma unroll
            for (int c = 0; c < 4; c++) acc[a][b][c] = 0.0f;

    unsigned long long G2, C4_2, C3_2, C2_2, ONE2;
    unsigned long long accR[8];
    {
        const float g = GAMMA, c4 = 1.0f / 24.0f, c3 = 1.0f / 6.0f, c2 = 0.5f, o = 1.0f, z = 0.0f;
        PACK2(G2, g, g); PACK2(C4_2, c4, c4); PACK2(C3_2, c3, c3);
        PACK2(C2_2, c2, c2); PACK2(ONE2, o, o);
        unsigned long long zz; PACK2(zz, z, z);
#pragma unroll
        for (int i = 0; i < 8; i++) accR[i] = zz;
    }

    // precomputed ldmatrix lane addressing pieces
    const int aRow  = wm * 64 + (lane & 15);          // + mt*16
    const int aKsel = (lane >> 4) * 16;               // 0 or 16 (within 32B k-chunk)
    const int bRow  = wn * 32 + (lane & 7);           // + nt*8
    const int bKsel = ((lane >> 3) & 1) * 16;

    for (int t = 0; t < NT; ++t) {
        if (t == NT - 1) { CP_WAIT(0); } else { CP_WAIT(1); }
        __syncthreads();

        const uint32_t bb = bBase + (t & 1) * TILEB;

#pragma unroll
        for (int kc = 0; kc < 8; kc++) {
            const int kb = kc * 32;
            uint32_t af[4][4];
#pragma unroll
            for (int mt = 0; mt < 4; mt++) {
                const int row = aRow + mt * 16;
                const int k = kb + aKsel;
                uint32_t addr = aBase + (k >> 7) * KCHUNK + SW128(row * 128 + (k & 127));
                asm volatile("ldmatrix.sync.aligned.m8n8.x4.shared.b16 {%0,%1,%2,%3}, [%4];\n"
                             : "=r"(af[mt][0]), "=r"(af[mt][1]), "=r"(af[mt][2]), "=r"(af[mt][3])
                             : "r"(addr));
            }
#pragma unroll
            for (int nt = 0; nt < 4; nt++) {
                const int nrow = bRow + nt * 8;
                const int k = kb + bKsel;
                uint32_t b0, b1;
                uint32_t addr = bb + (k >> 7) * KCHUNK + SW128(nrow * 128 + (k & 127));
                asm volatile("ldmatrix.sync.aligned.m8n8.x2.shared.b16 {%0,%1}, [%2];\n"
                             : "=r"(b0), "=r"(b1) : "r"(addr));
#pragma unroll
                for (int mt = 0; mt < 4; mt++) {
                    asm volatile(
                        "mma.sync.aligned.m16n8k32.row.col.f32.e4m3.e4m3.f32 "
                        "{%0,%1,%2,%3}, {%4,%5,%6,%7}, {%8,%9}, {%0,%1,%2,%3};\n"
                        : "+f"(acc[mt][nt][0]), "+f"(acc[mt][nt][1]),
                          "+f"(acc[mt][nt][2]), "+f"(acc[mt][nt][3])
                        : "r"(af[mt][0]), "r"(af[mt][1]), "r"(af[mt][2]), "r"(af[mt][3]),
                          "r"(b0), "r"(b1));
                }
            }
        }
        __syncthreads();   // all reads of buffer (t&1) done before overwrite

        if (t + 2 < NT) {
            load_tile(bBase + (t & 1) * TILEB, Xb + (size_t)(colBase0 + (t + 2) * BN) * 256, tid);
            CP_COMMIT();
        }

        // maskless epilogue: sum exp(gamma*W) over the tile, poly4 in f32x2
#pragma unroll
        for (int mt = 0; mt < 4; mt++) {
#pragma unroll
            for (int nt = 0; nt < 4; nt++) {
                unsigned long long d2, w2, e2;
                PACK2(d2, acc[mt][nt][0], acc[mt][nt][1]);
                MUL2(w2, d2, G2);
                FMA2(e2, w2, C4_2, C3_2);
                FMA2(e2, e2, w2, C2_2);
                FMA2(e2, e2, w2, ONE2);
                FMA2(e2, e2, w2, ONE2);
                ADD2(accR[mt * 2], accR[mt * 2], e2);

                PACK2(d2, acc[mt][nt][2], acc[mt][nt][3]);
                MUL2(w2, d2, G2);
                FMA2(e2, w2, C4_2, C3_2);
                FMA2(e2, e2, w2, C2_2);
                FMA2(e2, e2, w2, ONE2);
                FMA2(e2, e2, w2, ONE2);
                ADD2(accR[mt * 2 + 1], accR[mt * 2 + 1], e2);

                acc[mt][nt][0] = 0.0f; acc[mt][nt][1] = 0.0f;
                acc[mt][nt][2] = 0.0f; acc[mt][nt][3] = 0.0f;
            }
        }
    }

    // reduce: lanes in a quad share the same rows -> shfl, then smem, then global
#pragma unroll
    for (int i = 0; i < 8; i++) {
        float vlo, vhi;
        UNPACK2(vlo, vhi, accR[i]);
        float v = vlo + vhi;
        v += __shfl_xor_sync(0xffffffffu, v, 1);
        v += __shfl_xor_sync(0xffffffffu, v, 2);
        if ((lane & 3) == 0) {
            int r = wm * 64 + (i >> 1) * 16 + (lane >> 2) + (i & 1) * 8;
            atomicAdd(&sAll[r], v);
        }
    }
    __syncthreads();
    if (tid < BM) atomicAdd(&g_all[rowBase + tid], sAll[tid]);
}

// ---------------- exact same-class correction (fp32) ----------------

__global__ __launch_bounds__(256)
void bhl_corr_kernel(const float* __restrict__ X) {
    __shared__ float rows[16][260];
    __shared__ int sm[16];
    const int c = blockIdx.x, tid = threadIdx.x;
    int K = g_cnt[c];
    if (K > 16) K = 16;
    if (tid < 16) sm[tid] = (tid < K) ? g_members[c * 16 + tid] : 0;
    __syncthreads();
#pragma unroll
    for (int f = tid; f < 1024; f += 256) {
        int row = f >> 6, q = f & 63;
        if (row < K) {
            float4 v = *(const float4*)(X + (size_t)sm[row] * DIMK + q * 4);
            rows[row][q * 4 + 0] = v.x; rows[row][q * 4 + 1] = v.y;
            rows[row][q * 4 + 2] = v.z; rows[row][q * 4 + 3] = v.w;
        }
    }
    __syncthreads();
    const int i = tid >> 4, j = tid & 15;
    float dot = 0.0f;
#pragma unroll 8
    for (int d = 0; d < DIMK; d++) dot += rows[i][d] * rows[j][d];
    float w = fminf(fmaxf(dot * GAMMA, -16.0f), 16.0f);
    const bool valid = (i < K) && (j < K);
    float epos  = (valid && i != j) ? __expf(-w) : 0.0f;
    float esame = valid ? __expf(w) : 0.0f;
#pragma unroll
    for (int o = 8; o; o >>= 1) {
        epos  += __shfl_xor_sync(0xffffffffu, epos, o);
        esame += __shfl_xor_sync(0xffffffffu, esame, o);
    }
    if (j == 0 && i < K) {
        g_pos[sm[i]]  = epos;
        g_same[sm[i]] = esame;
    }
}

__global__ void bhl_finalize_kernel(float* __restrict__ out) {
    __shared__ float red[256];
    const int tid = threadIdx.x;
    const int r = blockIdx.x * 256 + tid;
    red[tid] = __logf(g_pos[r] * (g_all[r] - g_same[r]));
    __syncthreads();
    for (int o = 128; o; o >>= 1) {
        if (tid < o) red[tid] += red[tid + o];
        __syncthreads();
    }
    if (tid == 0) atomicAdd(out, red[0] * (1.0f / (float)BATCH));
}

extern "C" void kernel_launch(void* const* d_in, const int* in_sizes, int n_in,
                              void* d_out, int out_size) {
    const float* X = (const float*)d_in[0];
    const int*   T = (const int*)d_in[1];
    float* out = (float*)d_out;

    cudaFuncSetAttribute(bhl_main_kernel, cudaFuncAttributeMaxDynamicSharedMemorySize, SMEM_DYN);

    bhl_convert_kernel<<<(BATCH * DIMK / 4) / 256, 256>>>(X, out);
    bhl_bucket_kernel<<<BATCH / 256, 256>>>(T);
    dim3 grid(BATCH / BM, NSPLIT);
    bhl_main_kernel<<<grid, 256, SMEM_DYN>>>();
    bhl_corr_kernel<<<NCLS, 256>>>(X);
    bhl_finalize_kernel<<<BATCH / 256, 256>>>(out);
}

// round 6
// speedup vs baseline: 2.8452x; 2.8452x over previous
#include <cuda_runtime.h>
#include <cuda_bf16.h>
#include <cstdint>

// BatchHardLoss round 5: bf16 mma.sync + SYMMETRY (upper-triangle tiles only,
// row+column accumulation) + maskless f32x2 poly-exp epilogue + exact fp32
// same-class correction.

#define BATCH 8192
#define DIMK  256
#define NCLS  512
#define GAMMA 0.001f

static __device__ float g_all[BATCH];    // sum_j exp(+gamma*W_ij), all j incl self
static __device__ float g_pos[BATCH];    // exact fp32: sum_{same,j!=i} exp(-gamma*W_ij)
static __device__ float g_same[BATCH];   // exact fp32: sum_{same incl self} exp(+gamma*W_ij)
static __device__ int   g_cnt[NCLS];
static __device__ int   g_members[NCLS * 16];
static __device__ __nv_bfloat16 g_Xb[BATCH * DIMK];

constexpr int BM = 128;
constexpr int NBLK = BATCH / BM;            // 64 row/col blocks
constexpr int NPAIR = NBLK * (NBLK + 1) / 2; // 2080 upper-triangle tile pairs
constexpr int GRID = 296;                    // 8 CTAs do 8 pairs, 288 do 7 (=2080)
constexpr int KCHUNK = 16384;                // 128 rows x 64 halves (128B) SW128 chunk
constexpr int ATILE = 65536;                 // A resident: 128 x 256 bf16
constexpr int SMEM_DYN = ATILE + 2 * KCHUNK + 1024;

#define SW128(o) ((o) ^ (((o) >> 3) & 0x70))

__device__ __forceinline__ void cp_async16(uint32_t dst, const void* src) {
    asm volatile("cp.async.cg.shared.global [%0], [%1], 16;\n" :: "r"(dst), "l"(src));
}
#define CP_COMMIT() asm volatile("cp.async.commit_group;\n" ::: "memory")
#define CP_WAIT(N)  asm volatile("cp.async.wait_group %0;\n" :: "n"(N) : "memory")

#define PACK2(d, a, b)    asm("mov.b64 %0, {%1,%2};" : "=l"(d) : "f"(a), "f"(b))
#define UNPACK2(a, b, s)  asm("mov.b64 {%0,%1}, %2;" : "=f"(a), "=f"(b) : "l"(s))
#define MUL2(d, a, b)     asm("mul.rn.f32x2 %0, %1, %2;" : "=l"(d) : "l"(a), "l"(b))
#define ADD2(d, a, b)     asm("add.rn.f32x2 %0, %1, %2;" : "=l"(d) : "l"(a), "l"(b))
#define FMA2(d, a, b, c)  asm("fma.rn.f32x2 %0, %1, %2, %3;" : "=l"(d) : "l"(a), "l"(b), "l"(c))

// ---------------- small kernels ----------------

__global__ void bhl_convert_kernel(const float* __restrict__ X, float* __restrict__ out) {
    int i = blockIdx.x * blockDim.x + threadIdx.x;   // float4 index
    float4 v = ((const float4*)X)[i];
    uint32_t lo = ((uint32_t)__bfloat16_as_ushort(__float2bfloat16_rn(v.y)) << 16)
                |  (uint32_t)__bfloat16_as_ushort(__float2bfloat16_rn(v.x));
    uint32_t hi = ((uint32_t)__bfloat16_as_ushort(__float2bfloat16_rn(v.w)) << 16)
                |  (uint32_t)__bfloat16_as_ushort(__float2bfloat16_rn(v.z));
    ((uint2*)g_Xb)[i] = make_uint2(lo, hi);
    if (i < BATCH) g_all[i] = 0.0f;
    if (i < NCLS)  g_cnt[i] = 0;
    if (i == 0)    out[0] = 0.0f;
}

__global__ void bhl_bucket_kernel(const int* __restrict__ T) {
    int i = blockIdx.x * blockDim.x + threadIdx.x;
    if (i < BATCH) {
        int c = T[i];
        int s = atomicAdd(&g_cnt[c], 1);
        if (s < 16) g_members[c * 16 + s] = i;
    }
}

// ---------------- main kernel ----------------

// full A tile: 128 rows x 256 bf16 (512B/row) into 4 SW128 chunks
__device__ __forceinline__ void load_tileA(uint32_t sdst, const char* srcRow0, int tid) {
#pragma unroll
    for (int i = 0; i < 16; i++) {
        int s = i * 256 + tid;            // 16B segment 0..4095
        int row = s >> 5;
        int seg = s & 31;
        int chunk = seg >> 3, w = seg & 7;
        uint32_t soff = chunk * KCHUNK + SW128(row * 128 + w * 16);
        cp_async16(sdst + soff, srcRow0 + (size_t)row * 512 + seg * 16);
    }
}

// one B k-chunk: 128 rows x 64 halves (128B/row)
__device__ __forceinline__ void load_chunkB(uint32_t sdst, const char* srcRow0, int kc, int tid) {
#pragma unroll
    for (int i = 0; i < 4; i++) {
        int s = i * 256 + tid;            // 0..1023
        int n = s >> 3, w = s & 7;
        uint32_t soff = SW128(n * 128 + w * 16);
        cp_async16(sdst + soff, srcRow0 + (size_t)n * 512 + kc * 128 + w * 16);
    }
}

__global__ __launch_bounds__(256, 2)
void bhl_main_kernel() {
    extern __shared__ char dynsmem[];
    __shared__ float sAll[BM];
    __shared__ float sCol[BM];

    const int tid  = threadIdx.x;
    const int lane = tid & 31;
    const int wid  = tid >> 5;
    const int wm   = wid >> 2;           // 0..1
    const int wn   = wid & 3;            // 0..3
    const int bid  = blockIdx.x;

    // pair range: first 8 CTAs get 8 pairs, rest 7
    const int pstart = bid * 7 + min(bid, 8);
    const int pcount = 7 + (bid < 8 ? 1 : 0);

    // decode pstart -> (I, J) in upper triangle (row-major runs)
    int I = 0, s = 0;
    while (s + (NBLK - I) <= pstart) { s += NBLK - I; I++; }
    int J = I + (pstart - s);

    uint32_t sb = (uint32_t)__cvta_generic_to_shared(dynsmem);
    sb = (sb + 1023) & ~1023u;
    const uint32_t aBase = sb;
    const uint32_t bBase = sb + ATILE;

    const char* Xb = (const char*)g_Xb;

    // prologue: A(I) + B(J) chunk0 -> group; B chunk1 -> group
    load_tileA(aBase, Xb + (size_t)I * BM * 512, tid);
    load_chunkB(bBase, Xb + (size_t)J * BM * 512, 0, tid);
    CP_COMMIT();
    load_chunkB(bBase + KCHUNK, Xb + (size_t)J * BM * 512, 1, tid);
    CP_COMMIT();

    float acc[4][4][4];
#pragma unroll
    for (int a = 0; a < 4; a++)
#pragma unroll
        for (int b = 0; b < 4; b++)
#pragma unroll
            for (int c = 0; c < 4; c++) acc[a][b][c] = 0.0f;

    unsigned long long G2, C4_2, C3_2, C2_2, ONE2, ZERO2;
    unsigned long long accR[8], colAcc[4];
    {
        const float g = GAMMA, c4 = 1.0f / 24.0f, c3 = 1.0f / 6.0f, c2 = 0.5f, o = 1.0f, z = 0.0f;
        PACK2(G2, g, g); PACK2(C4_2, c4, c4); PACK2(C3_2, c3, c3);
        PACK2(C2_2, c2, c2); PACK2(ONE2, o, o); PACK2(ZERO2, z, z);
#pragma unroll
        for (int i = 0; i < 8; i++) accR[i] = ZERO2;
#pragma unroll
        for (int i = 0; i < 4; i++) colAcc[i] = ZERO2;
    }

    const int aRow  = wm * 64 + (lane & 15);
    const int aKsel = (lane >> 4);               // +0/+1 16B segment
    const int bRow  = wn * 32 + (lane & 7);
    const int bKsel = ((lane >> 3) & 1);

    bool aNew = false;

    for (int pi = 0; pi < pcount; ++pi) {
        const bool last = (pi == pcount - 1);
        int In = I, Jn = J + 1;
        if (Jn == NBLK) { In = I + 1; Jn = In; }
        const char* BnextRow0 = Xb + (size_t)Jn * BM * 512;

#pragma unroll
        for (int c = 0; c < 4; c++) {
            if (c == 0 && aNew) { CP_WAIT(0); } else { CP_WAIT(1); }
            __syncthreads();

            const uint32_t aC = aBase + c * KCHUNK;
            const uint32_t bC = bBase + (c & 1) * KCHUNK;

#pragma unroll
            for (int ks = 0; ks < 4; ks++) {
                uint32_t af[4][4];
#pragma unroll
                for (int mt = 0; mt < 4; mt++) {
                    int row = aRow + mt * 16;
                    int kseg = ks * 2 + aKsel;
                    uint32_t addr = aC + SW128(row * 128 + kseg * 16);
                    asm volatile("ldmatrix.sync.aligned.m8n8.x4.shared.b16 {%0,%1,%2,%3}, [%4];\n"
                                 : "=r"(af[mt][0]), "=r"(af[mt][1]), "=r"(af[mt][2]), "=r"(af[mt][3])
                                 : "r"(addr));
                }
#pragma unroll
                for (int nt = 0; nt < 4; nt++) {
                    int n = bRow + nt * 8;
                    int kseg = ks * 2 + bKsel;
                    uint32_t b0, b1;
                    uint32_t addr = bC + SW128(n * 128 + kseg * 16);
                    asm volatile("ldmatrix.sync.aligned.m8n8.x2.shared.b16 {%0,%1}, [%2];\n"
                                 : "=r"(b0), "=r"(b1) : "r"(addr));
#pragma unroll
                    for (int mt = 0; mt < 4; mt++) {
                        asm volatile(
                            "mma.sync.aligned.m16n8k16.row.col.f32.bf16.bf16.f32 "
                            "{%0,%1,%2,%3}, {%4,%5,%6,%7}, {%8,%9}, {%0,%1,%2,%3};\n"
                            : "+f"(acc[mt][nt][0]), "+f"(acc[mt][nt][1]),
                              "+f"(acc[mt][nt][2]), "+f"(acc[mt][nt][3])
                            : "r"(af[mt][0]), "r"(af[mt][1]), "r"(af[mt][2]), "r"(af[mt][3]),
                              "r"(b0), "r"(b1));
                    }
                }
            }
            __syncthreads();   // buffer reads done before prefetch overwrites

            if (c < 2) {
                load_chunkB(bBase + (c & 1) * KCHUNK, Xb + (size_t)J * BM * 512, c + 2, tid);
            } else if (!last) {
                load_chunkB(bBase + (c & 1) * KCHUNK, BnextRow0, c - 2, tid);
            }
            CP_COMMIT();
        }

        // ---- epilogue: poly-exp, row + col accumulation ----
#pragma unroll
        for (int mt = 0; mt < 4; mt++) {
#pragma unroll
            for (int nt = 0; nt < 4; nt++) {
                unsigned long long d2, w2, e2;
                PACK2(d2, acc[mt][nt][0], acc[mt][nt][1]);
                MUL2(w2, d2, G2);
                FMA2(e2, w2, C4_2, C3_2);
                FMA2(e2, e2, w2, C2_2);
                FMA2(e2, e2, w2, ONE2);
                FMA2(e2, e2, w2, ONE2);
                ADD2(accR[mt * 2], accR[mt * 2], e2);
                ADD2(colAcc[nt], colAcc[nt], e2);

                PACK2(d2, acc[mt][nt][2], acc[mt][nt][3]);
                MUL2(w2, d2, G2);
                FMA2(e2, w2, C4_2, C3_2);
                FMA2(e2, e2, w2, C2_2);
                FMA2(e2, e2, w2, ONE2);
                FMA2(e2, e2, w2, ONE2);
                ADD2(accR[mt * 2 + 1], accR[mt * 2 + 1], e2);
                ADD2(colAcc[nt], colAcc[nt], e2);

                acc[mt][nt][0] = 0.0f; acc[mt][nt][1] = 0.0f;
                acc[mt][nt][2] = 0.0f; acc[mt][nt][3] = 0.0f;
            }
        }

        // ---- column flush (symmetric contribution to block J rows), off-diag only ----
        if (I != J) {
            if (tid < BM) sCol[tid] = 0.0f;
            __syncthreads();
#pragma unroll
            for (int nt = 0; nt < 4; nt++) {
                float vlo, vhi;
                UNPACK2(vlo, vhi, colAcc[nt]);
#pragma unroll
                for (int o = 4; o <= 16; o <<= 1) {
                    vlo += __shfl_xor_sync(0xffffffffu, vlo, o);
                    vhi += __shfl_xor_sync(0xffffffffu, vhi, o);
                }
                if (lane < 4) {
                    atomicAdd(&sCol[wn * 32 + nt * 8 + 2 * lane], vlo);
                    atomicAdd(&sCol[wn * 32 + nt * 8 + 2 * lane + 1], vhi);
                }
                colAcc[nt] = ZERO2;
            }
            __syncthreads();
            if (tid < BM) atomicAdd(&g_all[J * BM + tid], sCol[tid]);
        } else {
#pragma unroll
            for (int nt = 0; nt < 4; nt++) colAcc[nt] = ZERO2;
        }

        // ---- row flush when I changes (or at end) ----
        if (last || In != I) {
            if (tid < BM) sAll[tid] = 0.0f;
            __syncthreads();
#pragma unroll
            for (int i = 0; i < 8; i++) {
                float vlo, vhi;
                UNPACK2(vlo, vhi, accR[i]);
                float v = vlo + vhi;
                v += __shfl_xor_sync(0xffffffffu, v, 1);
                v += __shfl_xor_sync(0xffffffffu, v, 2);
                if ((lane & 3) == 0) {
                    int r = wm * 64 + (i >> 1) * 16 + (lane >> 2) + (i & 1) * 8;
                    atomicAdd(&sAll[r], v);
                }
                accR[i] = ZERO2;
            }
            __syncthreads();
            if (tid < BM) atomicAdd(&g_all[I * BM + tid], sAll[tid]);
        }

        // ---- A reload for next pair if row block changes ----
        aNew = false;
        if (!last && In != I) {
            load_tileA(aBase, Xb + (size_t)In * BM * 512, tid);
            CP_COMMIT();
            aNew = true;
        }
        I = In; J = Jn;
    }
}

// ---------------- exact same-class correction (fp32, float4 LDS) ----------------

__global__ __launch_bounds__(256)
void bhl_corr_kernel(const float* __restrict__ X) {
    __shared__ float rows[16][260];        // 260*4B row stride: float4-aligned, conflict-light
    __shared__ int sm[16];
    const int c = blockIdx.x, tid = threadIdx.x;
    int K = g_cnt[c];
    if (K > 16) K = 16;
    if (tid < 16) sm[tid] = (tid < K) ? g_members[c * 16 + tid] : 0;
    __syncthreads();
#pragma unroll
    for (int f = tid; f < 1024; f += 256) {
        int row = f >> 6, q = f & 63;
        if (row < K) {
            float4 v = *(const float4*)(X + (size_t)sm[row] * DIMK + q * 4);
            *(float4*)&rows[row][q * 4] = v;
        }
    }
    __syncthreads();
    const int i = tid >> 4, j = tid & 15;
    const float4* ri = (const float4*)&rows[i][0];
    const float4* rj = (const float4*)&rows[j][0];
    float d0 = 0.0f, d1 = 0.0f, d2 = 0.0f, d3 = 0.0f;
#pragma unroll
    for (int d = 0; d < 64; d++) {
        float4 a = ri[d], b = rj[d];
        d0 += a.x * b.x; d1 += a.y * b.y; d2 += a.z * b.z; d3 += a.w * b.w;
    }
    float dot = (d0 + d1) + (d2 + d3);
    float w = fminf(fmaxf(dot * GAMMA, -16.0f), 16.0f);
    const bool valid = (i < K) && (j < K);
    float epos  = (valid && i != j) ? __expf(-w) : 0.0f;
    float esame = valid ? __expf(w) : 0.0f;
#pragma unroll
    for (int o = 8; o; o >>= 1) {
        epos  += __shfl_xor_sync(0xffffffffu, epos, o);
        esame += __shfl_xor_sync(0xffffffffu, esame, o);
    }
    if (j == 0 && i < K) {
        g_pos[sm[i]]  = epos;
        g_same[sm[i]] = esame;
    }
}

__global__ void bhl_finalize_kernel(float* __restrict__ out) {
    __shared__ float red[256];
    const int tid = threadIdx.x;
    const int r = blockIdx.x * 256 + tid;
    red[tid] = __logf(g_pos[r] * (g_all[r] - g_same[r]));
    __syncthreads();
    for (int o = 128; o; o >>= 1) {
        if (tid < o) red[tid] += red[tid + o];
        __syncthreads();
    }
    if (tid == 0) atomicAdd(out, red[0] * (1.0f / (float)BATCH));
}

extern "C" void kernel_launch(void* const* d_in, const int* in_sizes, int n_in,
                              void* d_out, int out_size) {
    const float* X = (const float*)d_in[0];
    const int*   T = (const int*)d_in[1];
    float* out = (float*)d_out;

    cudaFuncSetAttribute(bhl_main_kernel, cudaFuncAttributeMaxDynamicSharedMemorySize, SMEM_DYN);

    bhl_convert_kernel<<<(BATCH * DIMK / 4) / 256, 256>>>(X, out);
    bhl_bucket_kernel<<<BATCH / 256, 256>>>(T);
    bhl_corr_kernel<<<NCLS, 256>>>(X);
    bhl_main_kernel<<<GRID, 256, SMEM_DYN>>>();
    bhl_finalize_kernel<<<BATCH / 256, 256>>>(out);
}

// round 7
// speedup vs baseline: 2.9376x; 1.0325x over previous
#include <cuda_runtime.h>
#include <cuda_bf16.h>
#include <cstdint>

// BatchHardLoss round 6: bf16 mma.sync, symmetry (upper triangle), 3-deep B ring
// with ONE barrier per k-chunk, zero-C first-slab HMMA, epilogue deferred into
// next pair's chunk0 (FMA/tensor overlap), direct-atomic column flush.

#define BATCH 8192
#define DIMK  256
#define NCLS  512
#define GAMMA 0.001f

static __device__ float g_all[BATCH];
static __device__ float g_pos[BATCH];
static __device__ float g_same[BATCH];
static __device__ int   g_cnt[NCLS];
static __device__ int   g_members[NCLS * 16];
static __device__ __nv_bfloat16 g_Xb[BATCH * DIMK];

constexpr int BM = 128;
constexpr int NBLK = BATCH / BM;             // 64
constexpr int GRID = 296;                    // 8 CTAs x8 pairs + 288 x7 = 2080
constexpr int KCHUNK = 16384;                // 128 rows x 128B SW128 chunk
constexpr int ATILE = 65536;                 // A resident: 128 x 256 bf16
constexpr int SMEM_DYN = ATILE + 3 * KCHUNK; // 112 KB (14 x 8KB granules)

#define SW128(o) ((o) ^ (((o) >> 3) & 0x70))

__device__ __forceinline__ void cp_async16(uint32_t dst, const void* src) {
    asm volatile("cp.async.cg.shared.global [%0], [%1], 16;\n" :: "r"(dst), "l"(src));
}
#define CP_COMMIT() asm volatile("cp.async.commit_group;\n" ::: "memory")
#define CP_WAIT(N)  asm volatile("cp.async.wait_group %0;\n" :: "n"(N) : "memory")

#define PACK2(d, a, b)    asm("mov.b64 %0, {%1,%2};" : "=l"(d) : "f"(a), "f"(b))
#define UNPACK2(a, b, s)  asm("mov.b64 {%0,%1}, %2;" : "=f"(a), "=f"(b) : "l"(s))
#define MUL2(d, a, b)     asm("mul.rn.f32x2 %0, %1, %2;" : "=l"(d) : "l"(a), "l"(b))
#define ADD2(d, a, b)     asm("add.rn.f32x2 %0, %1, %2;" : "=l"(d) : "l"(a), "l"(b))
#define FMA2(d, a, b, c)  asm("fma.rn.f32x2 %0, %1, %2, %3;" : "=l"(d) : "l"(a), "l"(b), "l"(c))

// ---------------- small kernels ----------------

__global__ void bhl_convert_kernel(const float* __restrict__ X,
                                   const int* __restrict__ T,
                                   float* __restrict__ out) {
    int i = blockIdx.x * blockDim.x + threadIdx.x;   // float4 index
    float4 v = ((const float4*)X)[i];
    uint32_t lo = ((uint32_t)__bfloat16_as_ushort(__float2bfloat16_rn(v.y)) << 16)
                |  (uint32_t)__bfloat16_as_ushort(__float2bfloat16_rn(v.x));
    uint32_t hi = ((uint32_t)__bfloat16_as_ushort(__float2bfloat16_rn(v.w)) << 16)
                |  (uint32_t)__bfloat16_as_ushort(__float2bfloat16_rn(v.z));
    ((uint2*)g_Xb)[i] = make_uint2(lo, hi);
    if (i < BATCH) {
        g_all[i] = 0.0f;
        int c = T[i];
        int s = atomicAdd(&g_cnt[c], 1);
        if (s < 16) g_members[c * 16 + s] = i;
    }
    if (i == 0) out[0] = 0.0f;
}

__global__ void bhl_zero_cnt_kernel() {
    int i = threadIdx.x + blockIdx.x * blockDim.x;
    if (i < NCLS) g_cnt[i] = 0;
}

// ---------------- main kernel ----------------

__device__ __forceinline__ void load_tileA(uint32_t sdst, const char* srcRow0, int tid) {
#pragma unroll
    for (int i = 0; i < 16; i++) {
        int s = i * 256 + tid;
        int row = s >> 5;
        int seg = s & 31;
        int chunk = seg >> 3, w = seg & 7;
        uint32_t soff = chunk * KCHUNK + SW128(row * 128 + w * 16);
        cp_async16(sdst + soff, srcRow0 + (size_t)row * 512 + seg * 16);
    }
}

__device__ __forceinline__ void load_chunkB(uint32_t sdst, const char* srcRow0, int kc, int tid) {
#pragma unroll
    for (int i = 0; i < 4; i++) {
        int s = i * 256 + tid;
        int n = s >> 3, w = s & 7;
        uint32_t soff = SW128(n * 128 + w * 16);
        cp_async16(sdst + soff, srcRow0 + (size_t)n * 512 + kc * 128 + w * 16);
    }
}

__global__ __launch_bounds__(256, 2)
void bhl_main_kernel() {
    extern __shared__ char dynsmem[];

    const int tid  = threadIdx.x;
    const int lane = tid & 31;
    const int wid  = tid >> 5;
    const int wm   = wid >> 2;
    const int wn   = wid & 3;
    const int bid  = blockIdx.x;

    const int pstart = bid * 7 + min(bid, 8);
    const int pcount = 7 + (bid < 8 ? 1 : 0);

    int I = 0, s = 0;
    while (s + (NBLK - I) <= pstart) { s += NBLK - I; I++; }
    int J = I + (pstart - s);

    const uint32_t sb = (uint32_t)__cvta_generic_to_shared(dynsmem);
    const uint32_t aBase = sb;
    const uint32_t bBase = sb + ATILE;

    const char* Xb = (const char*)g_Xb;

    // prime: group0 = A(all) + B chunk0; group1 = B chunk1
    load_tileA(aBase, Xb + (size_t)I * BM * 512, tid);
    load_chunkB(bBase, Xb + (size_t)J * BM * 512, 0, tid);
    CP_COMMIT();
    load_chunkB(bBase + KCHUNK, Xb + (size_t)J * BM * 512, 1, tid);
    CP_COMMIT();

    float acc[4][4][4];
#pragma unroll
    for (int a = 0; a < 4; a++)
#pragma unroll
        for (int b = 0; b < 4; b++)
#pragma unroll
            for (int c = 0; c < 4; c++) acc[a][b][c] = 0.0f;

    unsigned long long G2, C4_2, C3_2, C2_2, ONE2, ZERO2;
    unsigned long long accR[8], colAcc[4];
    {
        const float g = GAMMA, c4 = 1.0f / 24.0f, c3 = 1.0f / 6.0f, c2 = 0.5f, o = 1.0f, z = 0.0f;
        PACK2(G2, g, g); PACK2(C4_2, c4, c4); PACK2(C3_2, c3, c3);
        PACK2(C2_2, c2, c2); PACK2(ONE2, o, o); PACK2(ZERO2, z, z);
#pragma unroll
        for (int i = 0; i < 8; i++) accR[i] = ZERO2;
#pragma unroll
        for (int i = 0; i < 4; i++) colAcc[i] = ZERO2;
    }
    const float zf = 0.0f;

    const int aRow  = wm * 64 + (lane & 15);
    const int aKsel = (lane >> 4);
    const int bRow  = wn * 32 + (lane & 7);
    const int bKsel = ((lane >> 3) & 1);

    int oldI = 0, oldJ = 0;
    bool haveOld = false;
    bool reloadedA = false;
    int gchunk = 0;          // global chunk counter (ring index)

    // ---- epilogue as a lambda: poly-exp old acc into accR/colAcc + col flush ----
    auto epilogue_and_colflush = [&]() {
#pragma unroll
        for (int mt = 0; mt < 4; mt++) {
#pragma unroll
            for (int nt = 0; nt < 4; nt++) {
                unsigned long long d2, w2, e2;
                PACK2(d2, acc[mt][nt][0], acc[mt][nt][1]);
                MUL2(w2, d2, G2);
                FMA2(e2, w2, C4_2, C3_2);
                FMA2(e2, e2, w2, C2_2);
                FMA2(e2, e2, w2, ONE2);
                FMA2(e2, e2, w2, ONE2);
                ADD2(accR[mt * 2], accR[mt * 2], e2);
                ADD2(colAcc[nt], colAcc[nt], e2);

                PACK2(d2, acc[mt][nt][2], acc[mt][nt][3]);
                MUL2(w2, d2, G2);
                FMA2(e2, w2, C4_2, C3_2);
                FMA2(e2, e2, w2, C2_2);
                FMA2(e2, e2, w2, ONE2);
                FMA2(e2, e2, w2, ONE2);
                ADD2(accR[mt * 2 + 1], accR[mt * 2 + 1], e2);
                ADD2(colAcc[nt], colAcc[nt], e2);
            }
        }
        if (oldI != oldJ) {
#pragma unroll
            for (int nt = 0; nt < 4; nt++) {
                float vlo, vhi;
                UNPACK2(vlo, vhi, colAcc[nt]);
#pragma unroll
                for (int o = 4; o <= 16; o <<= 1) {
                    vlo += __shfl_xor_sync(0xffffffffu, vlo, o);
                    vhi += __shfl_xor_sync(0xffffffffu, vhi, o);
                }
                if (lane < 4) {
                    atomicAdd(&g_all[oldJ * BM + wn * 32 + nt * 8 + 2 * lane], vlo);
                    atomicAdd(&g_all[oldJ * BM + wn * 32 + nt * 8 + 2 * lane + 1], vhi);
                }
                colAcc[nt] = ZERO2;
            }
        } else {
#pragma unroll
            for (int nt = 0; nt < 4; nt++) colAcc[nt] = ZERO2;
        }
    };

    auto rowflush = [&](int Iblk) {
#pragma unroll
        for (int i = 0; i < 8; i++) {
            float vlo, vhi;
            UNPACK2(vlo, vhi, accR[i]);
            float v = vlo + vhi;
            v += __shfl_xor_sync(0xffffffffu, v, 1);
            v += __shfl_xor_sync(0xffffffffu, v, 2);
            if ((lane & 3) == 0) {
                int r = wm * 64 + (i >> 1) * 16 + (lane >> 2) + (i & 1) * 8;
                atomicAdd(&g_all[Iblk * BM + r], v);
            }
            accR[i] = ZERO2;
        }
    };

    for (int pi = 0; pi < pcount; ++pi) {
        const bool last = (pi == pcount - 1);
        int In = I, Jn = J + 1;
        if (Jn == NBLK) { In = I + 1; Jn = In; }
        const char* Brow  = Xb + (size_t)J  * BM * 512;
        const char* BrowN = Xb + (size_t)Jn * BM * 512;

#pragma unroll
        for (int kc = 0; kc < 4; kc++) {
            if (kc == 0 && reloadedA) { CP_WAIT(0); reloadedA = false; }
            else { CP_WAIT(1); }
            __syncthreads();

            // deferred epilogue of previous pair overlaps with this chunk's MMA
            if (kc == 0 && haveOld) { epilogue_and_colflush(); haveOld = false; }

            const uint32_t aC = aBase + kc * KCHUNK;
            const uint32_t bC = bBase + (uint32_t)(gchunk % 3) * KCHUNK;

#pragma unroll
            for (int ks = 0; ks < 4; ks++) {
                uint32_t af[4][4];
#pragma unroll
                for (int mt = 0; mt < 4; mt++) {
                    int row = aRow + mt * 16;
                    int kseg = ks * 2 + aKsel;
                    uint32_t addr = aC + SW128(row * 128 + kseg * 16);
                    asm volatile("ldmatrix.sync.aligned.m8n8.x4.shared.b16 {%0,%1,%2,%3}, [%4];\n"
                                 : "=r"(af[mt][0]), "=r"(af[mt][1]), "=r"(af[mt][2]), "=r"(af[mt][3])
                                 : "r"(addr));
                }
#pragma unroll
                for (int nt = 0; nt < 4; nt++) {
                    int n = bRow + nt * 8;
                    int kseg = ks * 2 + bKsel;
                    uint32_t b0, b1;
                    uint32_t addr = bC + SW128(n * 128 + kseg * 16);
                    asm volatile("ldmatrix.sync.aligned.m8n8.x2.shared.b16 {%0,%1}, [%2];\n"
                                 : "=r"(b0), "=r"(b1) : "r"(addr));
                    if (kc == 0 && ks == 0) {
#pragma unroll
                        for (int mt = 0; mt < 4; mt++) {
                            asm volatile(
                                "mma.sync.aligned.m16n8k16.row.col.f32.bf16.bf16.f32 "
                                "{%0,%1,%2,%3}, {%4,%5,%6,%7}, {%8,%9}, {%10,%10,%10,%10};\n"
                                : "=f"(acc[mt][nt][0]), "=f"(acc[mt][nt][1]),
                                  "=f"(acc[mt][nt][2]), "=f"(acc[mt][nt][3])
                                : "r"(af[mt][0]), "r"(af[mt][1]), "r"(af[mt][2]), "r"(af[mt][3]),
                                  "r"(b0), "r"(b1), "f"(zf));
                        }
                    } else {
#pragma unroll
                        for (int mt = 0; mt < 4; mt++) {
                            asm volatile(
                                "mma.sync.aligned.m16n8k16.row.col.f32.bf16.bf16.f32 "
                                "{%0,%1,%2,%3}, {%4,%5,%6,%7}, {%8,%9}, {%0,%1,%2,%3};\n"
                                : "+f"(acc[mt][nt][0]), "+f"(acc[mt][nt][1]),
                                  "+f"(acc[mt][nt][2]), "+f"(acc[mt][nt][3])
                                : "r"(af[mt][0]), "r"(af[mt][1]), "r"(af[mt][2]), "r"(af[mt][3]),
                                  "r"(b0), "r"(b1));
                        }
                    }
                }
            }

            // prefetch chunk gchunk+2 into ring slot (gchunk+2)%3; always commit
            if (kc < 2) {
                load_chunkB(bBase + (uint32_t)((gchunk + 2) % 3) * KCHUNK, Brow, kc + 2, tid);
            } else if (!last) {
                load_chunkB(bBase + (uint32_t)((gchunk + 2) % 3) * KCHUNK, BrowN, kc - 2, tid);
            }
            CP_COMMIT();
            gchunk++;
        }

        oldI = I; oldJ = J; haveOld = true;

        if (last) {
            epilogue_and_colflush(); haveOld = false;
            rowflush(I);
        } else if (In != I) {
            __syncthreads();                 // all warps done reading A
            epilogue_and_colflush(); haveOld = false;
            rowflush(I);
            load_tileA(aBase, Xb + (size_t)In * BM * 512, tid);
            CP_COMMIT();
            reloadedA = true;
        }
        I = In; J = Jn;
    }
}

// ---------------- exact same-class correction (fp32) ----------------

__global__ __launch_bounds__(256)
void bhl_corr_kernel(const float* __restrict__ X) {
    __shared__ float rows[16][260];
    __shared__ int sm[16];
    const int c = blockIdx.x, tid = threadIdx.x;
    int K = g_cnt[c];
    if (K > 16) K = 16;
    if (tid < 16) sm[tid] = (tid < K) ? g_members[c * 16 + tid] : 0;
    __syncthreads();
#pragma unroll
    for (int f = tid; f < 1024; f += 256) {
        int row = f >> 6, q = f & 63;
        if (row < K) {
            float4 v = *(const float4*)(X + (size_t)sm[row] * DIMK + q * 4);
            *(float4*)&rows[row][q * 4] = v;
        }
    }
    __syncthreads();
    const int i = tid >> 4, j = tid & 15;
    const float4* ri = (const float4*)&rows[i][0];
    const float4* rj = (const float4*)&rows[j][0];
    float d0 = 0.0f, d1 = 0.0f, d2 = 0.0f, d3 = 0.0f;
#pragma unroll
    for (int d = 0; d < 64; d++) {
        float4 a = ri[d], b = rj[d];
        d0 += a.x * b.x; d1 += a.y * b.y; d2 += a.z * b.z; d3 += a.w * b.w;
    }
    float dot = (d0 + d1) + (d2 + d3);
    float w = fminf(fmaxf(dot * GAMMA, -16.0f), 16.0f);
    const bool valid = (i < K) && (j < K);
    float epos  = (valid && i != j) ? __expf(-w) : 0.0f;
    float esame = valid ? __expf(w) : 0.0f;
#pragma unroll
    for (int o = 8; o; o >>= 1) {
        epos  += __shfl_xor_sync(0xffffffffu, epos, o);
        esame += __shfl_xor_sync(0xffffffffu, esame, o);
    }
    if (j == 0 && i < K) {
        g_pos[sm[i]]  = epos;
        g_same[sm[i]] = esame;
    }
}

__global__ void bhl_finalize_kernel(float* __restrict__ out) {
    __shared__ float red[256];
    const int tid = threadIdx.x;
    const int r = blockIdx.x * 256 + tid;
    red[tid] = __logf(g_pos[r] * (g_all[r] - g_same[r]));
    __syncthreads();
    for (int o = 128; o; o >>= 1) {
        if (tid < o) red[tid] += red[tid + o];
        __syncthreads();
    }
    if (tid == 0) atomicAdd(out, red[0] * (1.0f / (float)BATCH));
}

extern "C" void kernel_launch(void* const* d_in, const int* in_sizes, int n_in,
                              void* d_out, int out_size) {
    const float* X = (const float*)d_in[0];
    const int*   T = (const int*)d_in[1];
    float* out = (float*)d_out;

    cudaFuncSetAttribute(bhl_main_kernel, cudaFuncAttributeMaxDynamicSharedMemorySize, SMEM_DYN);

    bhl_zero_cnt_kernel<<<2, 256>>>();
    bhl_convert_kernel<<<(BATCH * DIMK / 4) / 256, 256>>>(X, T, out);
    bhl_corr_kernel<<<NCLS, 256>>>(X);
    bhl_main_kernel<<<GRID, 256, SMEM_DYN>>>();
    bhl_finalize_kernel<<<BATCH / 256, 256>>>(out);
}